// round 4
// baseline (speedup 1.0000x reference)
#include <cuda_runtime.h>
#include <cuda_bf16.h>
#include <cstdint>

// ---------------------------------------------------------------------------
// GNNRepresentationNetwork  B=16, C=16, N=4096 (64x64), D_E=64, D_H=128, D_R=256
// Feature-major activations [b][d][n].  5 kernels:
//   embed (fused 2-layer MLP), gcn<64>, gcn<128>, gcn<128,MEAN>, readout.
// GCN identity (exact): relu(A(hW+b)) = relu((A h)W + s_n b), s_n = deg/(deg+1e-6)
// Mainloops: fma.rn.f32x2, weights pre-duplicated {w,w} in smem so the inner
// loop has ZERO register-packing MOVs: 6 LDS.128 + 32 FFMA2 per k per thread.
// ---------------------------------------------------------------------------

#define B_  16
#define N_  4096

typedef unsigned long long u64;

__device__ float g_bufA[B_ * 128 * N_];
__device__ float g_bufB[B_ * 128 * N_];
__device__ float g_part[B_ * 32 * 128];

__device__ __forceinline__ void fma2(u64& d, u64 a, u64 b) {
    asm("fma.rn.f32x2 %0, %1, %2, %0;" : "+l"(d) : "l"(a), "l"(b));
}
__device__ __forceinline__ u64 pack2(float lo, float hi) {
    u64 r; asm("mov.b64 %0, {%1, %2};" : "=l"(r) : "f"(lo), "f"(hi)); return r;
}
__device__ __forceinline__ float2 unpack2(u64 v) {
    float2 f; asm("mov.b64 {%0, %1}, %2;" : "=f"(f.x), "=f"(f.y) : "l"(v)); return f;
}
__device__ __forceinline__ float recip_deg(int deg) {
    return deg == 4 ? 0.2499999375f : (deg == 3 ? 0.3333332222f : 0.4999997500f);
}

// ---------------------------------------------------------------------------
// Fused embed MLP: out[b][d][n] = relu(relu(x W1 + b1) W2 + b2), D=64
// 256 threads: tx = tid&15 (8 n each), ty = tid>>4 (4 d each)
// Wd holds the 16xD weight k-tile duplicated {w,w} (16 x 128 floats).
// ---------------------------------------------------------------------------
__global__ void __launch_bounds__(256)
embed_kernel(const float* __restrict__ obs,
             const float* __restrict__ w1, const float* __restrict__ b1,
             const float* __restrict__ w2, const float* __restrict__ b2,
             float* __restrict__ out)
{
    __shared__ __align__(16) float Xs[16 * 128];   // obs tile
    __shared__ __align__(16) float Wd[16 * 128];   // dup weight k-tile (D=64)
    __shared__ __align__(16) float Hs[64 * 128];   // h1

    const int tid = threadIdx.x, tx = tid & 15, ty = tid >> 4;
    const int m0 = blockIdx.x * 128;
    const int b  = m0 >> 12, n0 = m0 & (N_ - 1);
    const float* xb = obs + (size_t)b * 16 * N_ + n0;

    // Stage obs tile: 16 rows x 128 floats = 512 float4, 2 per thread
    {
        const int i0 = tid, i1 = tid + 256;
        *reinterpret_cast<float4*>(&Xs[(i0 >> 5) * 128 + (i0 & 31) * 4]) =
            *(reinterpret_cast<const float4*>(xb + (size_t)(i0 >> 5) * N_) + (i0 & 31));
        *reinterpret_cast<float4*>(&Xs[(i1 >> 5) * 128 + (i1 & 31) * 4]) =
            *(reinterpret_cast<const float4*>(xb + (size_t)(i1 >> 5) * N_) + (i1 & 31));
    }
    // Stage W1 (16x64) duplicated: 256 source float4, 1 per thread -> 2 stores
    {
        const float4 w = *(reinterpret_cast<const float4*>(w1) + tid);
        const int f = tid * 4, r = f >> 6, d = f & 63;
        float* dst = &Wd[r * 128 + 2 * d];
        *reinterpret_cast<float4*>(dst)     = make_float4(w.x, w.x, w.y, w.y);
        *reinterpret_cast<float4*>(dst + 4) = make_float4(w.z, w.z, w.w, w.w);
    }
    __syncthreads();

    // Layer 1: acc[4 d][4 n-pairs]
    u64 acc[4][4];
#pragma unroll
    for (int dd = 0; dd < 4; dd++) {
        const float bv = b1[ty * 4 + dd];
        const u64 bp = pack2(bv, bv);
#pragma unroll
        for (int j = 0; j < 4; j++) acc[dd][j] = bp;
    }
#pragma unroll
    for (int k = 0; k < 16; k++) {
        const ulonglong2 a01 = *reinterpret_cast<const ulonglong2*>(&Xs[k * 128 + tx * 8]);
        const ulonglong2 a23 = *reinterpret_cast<const ulonglong2*>(&Xs[k * 128 + tx * 8 + 4]);
        const u64 a[4] = { a01.x, a01.y, a23.x, a23.y };
        const ulonglong2 w01 = *reinterpret_cast<const ulonglong2*>(&Wd[k * 128 + ty * 8]);
        const ulonglong2 w23 = *reinterpret_cast<const ulonglong2*>(&Wd[k * 128 + ty * 8 + 4]);
        const u64 wd[4] = { w01.x, w01.y, w23.x, w23.y };
#pragma unroll
        for (int dd = 0; dd < 4; dd++)
#pragma unroll
            for (int j = 0; j < 4; j++) fma2(acc[dd][j], wd[dd], a[j]);
    }
    // relu -> Hs
#pragma unroll
    for (int dd = 0; dd < 4; dd++) {
        float* hr = &Hs[(ty * 4 + dd) * 128 + tx * 8];
#pragma unroll
        for (int j = 0; j < 4; j += 2) {
            const float2 p0 = unpack2(acc[dd][j]), p1 = unpack2(acc[dd][j + 1]);
            float4 o = { fmaxf(p0.x, 0.f), fmaxf(p0.y, 0.f), fmaxf(p1.x, 0.f), fmaxf(p1.y, 0.f) };
            *reinterpret_cast<float4*>(hr + j * 2) = o;
        }
    }
    __syncthreads();

    // Layer 2: K=64 in 4 tiles of 16
    u64 acc2[4][4];
#pragma unroll
    for (int dd = 0; dd < 4; dd++) {
        const float bv = b2[ty * 4 + dd];
        const u64 bp = pack2(bv, bv);
#pragma unroll
        for (int j = 0; j < 4; j++) acc2[dd][j] = bp;
    }
    for (int kc = 0; kc < 64; kc += 16) {
        __syncthreads();
        {
            const float4 w = *(reinterpret_cast<const float4*>(w2 + kc * 64) + tid);
            const int f = tid * 4, r = f >> 6, d = f & 63;
            float* dst = &Wd[r * 128 + 2 * d];
            *reinterpret_cast<float4*>(dst)     = make_float4(w.x, w.x, w.y, w.y);
            *reinterpret_cast<float4*>(dst + 4) = make_float4(w.z, w.z, w.w, w.w);
        }
        __syncthreads();
#pragma unroll
        for (int k = 0; k < 16; k++) {
            const ulonglong2 a01 = *reinterpret_cast<const ulonglong2*>(&Hs[(kc + k) * 128 + tx * 8]);
            const ulonglong2 a23 = *reinterpret_cast<const ulonglong2*>(&Hs[(kc + k) * 128 + tx * 8 + 4]);
            const u64 a[4] = { a01.x, a01.y, a23.x, a23.y };
            const ulonglong2 w01 = *reinterpret_cast<const ulonglong2*>(&Wd[k * 128 + ty * 8]);
            const ulonglong2 w23 = *reinterpret_cast<const ulonglong2*>(&Wd[k * 128 + ty * 8 + 4]);
            const u64 wd[4] = { w01.x, w01.y, w23.x, w23.y };
#pragma unroll
            for (int dd = 0; dd < 4; dd++)
#pragma unroll
                for (int j = 0; j < 4; j++) fma2(acc2[dd][j], wd[dd], a[j]);
        }
    }

    float* ob = out + (size_t)b * 64 * N_ + n0 + tx * 8;
#pragma unroll
    for (int dd = 0; dd < 4; dd++) {
        float* orow = ob + (size_t)(ty * 4 + dd) * N_;
#pragma unroll
        for (int j = 0; j < 4; j += 2) {
            const float2 p0 = unpack2(acc2[dd][j]), p1 = unpack2(acc2[dd][j + 1]);
            float4 o = { fmaxf(p0.x, 0.f), fmaxf(p0.y, 0.f), fmaxf(p1.x, 0.f), fmaxf(p1.y, 0.f) };
            *reinterpret_cast<float4*>(orow + j * 2) = o;
        }
    }
}

// ---------------------------------------------------------------------------
// GCN layer: out[b][d][n] = relu( sum_k stencil(in[b][k])[n] * Wt[k][d] + s_n*bias[d] )
// D = 128. 256 threads: tx = tid&15 (8 n), ty = tid>>4 (8 d).
// Wd: 16 x 256 floats, duplicated {w,w}. Mainloop: 6 LDS.128 + 32 FFMA2 / k.
// MEAN: per-block partial sums instead of store (deterministic).
// ---------------------------------------------------------------------------
template <int K, bool MEAN>
__global__ void __launch_bounds__(256, 2)
gcn_kernel(const float* __restrict__ in, const float* __restrict__ Wt,
           const float* __restrict__ bias, float* __restrict__ out,
           float* __restrict__ part)
{
    __shared__ __align__(16) float Ls[16 * 256];   // halo window [n0-64, n0+192)
    __shared__ __align__(16) float As[16 * 128];   // stencil result
    __shared__ __align__(16) float Wd[16 * 256];   // dup weight k-tile

    const int tid = threadIdx.x, tx = tid & 15, ty = tid >> 4;
    const int m0 = blockIdx.x * 128;
    const int b  = m0 >> 12, n0 = m0 & (N_ - 1);
    const float* inb = in + (size_t)b * K * N_;

    u64 acc[8][4];
#pragma unroll
    for (int dd = 0; dd < 8; dd++)
#pragma unroll
        for (int j = 0; j < 4; j++) acc[dd][j] = 0ull;

    for (int kc = 0; kc < K; kc += 16) {
        // 1) Stage halo window: 16 rows x 256 floats (zero-padded ends)
#pragma unroll
        for (int i = 0; i < 4; i++) {
            const int idx = i * 256 + tid;
            const int r = idx >> 6, c4 = idx & 63;
            const int nw = n0 - 64 + c4 * 4;
            float4 v = make_float4(0.f, 0.f, 0.f, 0.f);
            if (nw >= 0 && nw < N_)
                v = *reinterpret_cast<const float4*>(inb + (size_t)(kc + r) * N_ + nw);
            *reinterpret_cast<float4*>(&Ls[r * 256 + c4 * 4]) = v;
        }
        // Stage weights duplicated: 512 source float4, 2 per thread -> 4 stores
        {
            const float4* Wg = reinterpret_cast<const float4*>(Wt + (size_t)kc * 128);
#pragma unroll
            for (int i = 0; i < 2; i++) {
                const int idx = i * 256 + tid;          // 0..511
                const float4 w = Wg[idx];
                const int f = idx * 4, r = f >> 7, d = f & 127;
                float* dst = &Wd[r * 256 + 2 * d];
                *reinterpret_cast<float4*>(dst)     = make_float4(w.x, w.x, w.y, w.y);
                *reinterpret_cast<float4*>(dst + 4) = make_float4(w.z, w.z, w.w, w.w);
            }
        }
        __syncthreads();

        // 2) Stencil: 512 float4 groups, 2 per thread
#pragma unroll
        for (int i = 0; i < 2; i++) {
            const int g  = i * 256 + tid;
            const int r  = g >> 5;
            const int j0 = (g & 31) * 4;
            const float* L = &Ls[r * 256];
            const float4 up = *reinterpret_cast<const float4*>(L + j0);
            const float4 dn = *reinterpret_cast<const float4*>(L + j0 + 128);
            const float4 c  = *reinterpret_cast<const float4*>(L + j0 + 64);
            const float lm = L[j0 + 63];
            const float rp = L[j0 + 68];
            const int n = n0 + j0;
            const bool lv = (n & 63) != 0;
            const bool rv = ((n + 3) & 63) != 63;
            const int dm = ((n >= 64) ? 1 : 0) + ((n < N_ - 64) ? 1 : 0);
            float4 o;
            o.x = (up.x + dn.x + (lv ? lm : 0.f) + c.y) * recip_deg(dm + (lv ? 1 : 0) + 1);
            o.y = (up.y + dn.y + c.x + c.z)             * recip_deg(dm + 2);
            o.z = (up.z + dn.z + c.y + c.w)             * recip_deg(dm + 2);
            o.w = (up.w + dn.w + c.z + (rv ? rp : 0.f)) * recip_deg(dm + 1 + (rv ? 1 : 0));
            *reinterpret_cast<float4*>(&As[r * 128 + j0]) = o;
        }
        __syncthreads();

        // 3) FFMA2 mainloop: 8n x 8d per thread, no MOVs
#pragma unroll
        for (int k = 0; k < 16; k++) {
            const ulonglong2 a01 = *reinterpret_cast<const ulonglong2*>(&As[k * 128 + tx * 8]);
            const ulonglong2 a23 = *reinterpret_cast<const ulonglong2*>(&As[k * 128 + tx * 8 + 4]);
            const u64 a[4] = { a01.x, a01.y, a23.x, a23.y };
            const ulonglong2 w01 = *reinterpret_cast<const ulonglong2*>(&Wd[k * 256 + ty * 16]);
            const ulonglong2 w23 = *reinterpret_cast<const ulonglong2*>(&Wd[k * 256 + ty * 16 + 4]);
            const ulonglong2 w45 = *reinterpret_cast<const ulonglong2*>(&Wd[k * 256 + ty * 16 + 8]);
            const ulonglong2 w67 = *reinterpret_cast<const ulonglong2*>(&Wd[k * 256 + ty * 16 + 12]);
            const u64 wd[8] = { w01.x, w01.y, w23.x, w23.y, w45.x, w45.y, w67.x, w67.y };
#pragma unroll
            for (int dd = 0; dd < 8; dd++)
#pragma unroll
                for (int j = 0; j < 4; j++) fma2(acc[dd][j], wd[dd], a[j]);
        }
        __syncthreads();
    }

    // Epilogue: scaled bias + relu
    float sc[8];
#pragma unroll
    for (int j = 0; j < 8; j++) {
        const int nn = n0 + tx * 8 + j;
        const int gi = nn >> 6, gj = nn & 63;
        const float fd = (float)((gi > 0) + (gi < 63) + (gj > 0) + (gj < 63));
        sc[j] = fd / (fd + 1e-6f);
    }

    if (!MEAN) {
        float* ob = out + (size_t)b * 128 * N_ + n0 + tx * 8;
#pragma unroll
        for (int dd = 0; dd < 8; dd++) {
            const float bv = __ldg(&bias[ty * 8 + dd]);
            float* orow = ob + (size_t)(ty * 8 + dd) * N_;
#pragma unroll
            for (int j = 0; j < 4; j += 2) {
                const float2 p0 = unpack2(acc[dd][j]), p1 = unpack2(acc[dd][j + 1]);
                float4 o;
                o.x = fmaxf(fmaf(sc[j * 2 + 0], bv, p0.x), 0.f);
                o.y = fmaxf(fmaf(sc[j * 2 + 1], bv, p0.y), 0.f);
                o.z = fmaxf(fmaf(sc[j * 2 + 2], bv, p1.x), 0.f);
                o.w = fmaxf(fmaf(sc[j * 2 + 3], bv, p1.y), 0.f);
                *reinterpret_cast<float4*>(orow + j * 2) = o;
            }
        }
    } else {
#pragma unroll
        for (int dd = 0; dd < 8; dd++) {
            const float bv = __ldg(&bias[ty * 8 + dd]);
            float s = 0.f;
#pragma unroll
            for (int j = 0; j < 4; j++) {
                const float2 p = unpack2(acc[dd][j]);
                s += fmaxf(fmaf(sc[j * 2 + 0], bv, p.x), 0.f)
                   + fmaxf(fmaf(sc[j * 2 + 1], bv, p.y), 0.f);
            }
#pragma unroll
            for (int off = 8; off > 0; off >>= 1)
                s += __shfl_xor_sync(0xffffffffu, s, off, 16);
            if (tx == 0)
                part[(size_t)blockIdx.x * 128 + ty * 8 + dd] = s;
        }
    }
}

// ---------------------------------------------------------------------------
// Readout: g[b] = mean partials; out = relu(relu(g r1 + b1) r2 + b2)
// ---------------------------------------------------------------------------
__global__ void __launch_bounds__(256)
readout_kernel(const float* __restrict__ part,
               const float* __restrict__ r1w, const float* __restrict__ r1b,
               const float* __restrict__ r2w, const float* __restrict__ r2b,
               float* __restrict__ out)
{
    __shared__ float gs[128];
    __shared__ float ts[256];
    const int b = blockIdx.x, t = threadIdx.x;

    if (t < 128) {
        float s = 0.f;
        const float* p = part + (size_t)b * 32 * 128 + t;
#pragma unroll
        for (int k = 0; k < 32; k++) s += p[k * 128];
        gs[t] = s * (1.0f / (float)N_);
    }
    __syncthreads();

    float a1 = r1b[t];
#pragma unroll 8
    for (int k = 0; k < 128; k++) a1 = fmaf(gs[k], r1w[k * 256 + t], a1);
    ts[t] = fmaxf(a1, 0.f);
    __syncthreads();

    float a2 = r2b[t];
#pragma unroll 8
    for (int k = 0; k < 256; k++) a2 = fmaf(ts[k], r2w[k * 256 + t], a2);
    out[b * 256 + t] = fmaxf(a2, 0.f);
}

// ---------------------------------------------------------------------------
extern "C" void kernel_launch(void* const* d_in, const int* in_sizes, int n_in,
                              void* d_out, int out_size)
{
    const float* obs  = (const float*)d_in[0];
    const float* e1_w = (const float*)d_in[1];
    const float* e1_b = (const float*)d_in[2];
    const float* e2_w = (const float*)d_in[3];
    const float* e2_b = (const float*)d_in[4];
    const float* g1_w = (const float*)d_in[5];
    const float* g1_b = (const float*)d_in[6];
    const float* g2_w = (const float*)d_in[7];
    const float* g2_b = (const float*)d_in[8];
    const float* g3_w = (const float*)d_in[9];
    const float* g3_b = (const float*)d_in[10];
    const float* r1_w = (const float*)d_in[11];
    const float* r1_b = (const float*)d_in[12];
    const float* r2_w = (const float*)d_in[13];
    const float* r2_b = (const float*)d_in[14];
    float* out = (float*)d_out;

    float *bufA, *bufB, *part;
    cudaGetSymbolAddress((void**)&bufA, g_bufA);
    cudaGetSymbolAddress((void**)&bufB, g_bufB);
    cudaGetSymbolAddress((void**)&part, g_part);

    const int GB = (B_ * N_) / 128;   // 512 blocks

    embed_kernel<<<GB, 256>>>(obs, e1_w, e1_b, e2_w, e2_b, bufB);
    gcn_kernel<64,  false><<<GB, 256>>>(bufB, g1_w, g1_b, bufA, nullptr);
    gcn_kernel<128, false><<<GB, 256>>>(bufA, g2_w, g2_b, bufB, nullptr);
    gcn_kernel<128, true ><<<GB, 256>>>(bufB, g3_w, g3_b, nullptr, part);
    readout_kernel<<<B_, 256>>>(part, r1_w, r1_b, r2_w, r2_b, out);
}